// round 2
// baseline (speedup 1.0000x reference)
#include <cuda_runtime.h>
#include <cstdint>
#include <math.h>

#define T_LEN 2048
#define BATCH 32
#define DIN   256
#define HID   256
#define NG    1024   // 4*HID
#define AOUT  18
#define GBLK  128    // recurrent CTAs; all co-resident on 148 SMs

typedef unsigned long long ull;

// ---------------- device scratch (no allocs allowed) ----------------
__device__ float g_Gx[(size_t)T_LEN * NG * BATCH];   // [t][n][b]  (256 MiB)
__device__ float g_hT[2][HID * BATCH];               // double-buffered h, [n*32+b]
__device__ unsigned g_bar_cnt;
__device__ unsigned g_bar_gen;

// packed f32x2 FMA (SASS FFMA2): 2 fp32 FMAs per instruction
__device__ __forceinline__ ull fma2(ull a, ull b, ull c) {
    ull d;
    asm("fma.rn.f32x2 %0, %1, %2, %3;" : "=l"(d) : "l"(a), "l"(b), "l"(c));
    return d;
}

// Grid barrier over exactly GBLK co-resident CTAs. State self-restores across
// graph replays (cnt returns to 0; gen only compared for equality).
__device__ __forceinline__ void grid_barrier() {
    __syncthreads();
    if (threadIdx.x == 0) {
        __threadfence();
        unsigned gen = *(volatile unsigned*)&g_bar_gen;
        if (atomicAdd(&g_bar_cnt, 1u) == GBLK - 1u) {
            atomicExch(&g_bar_cnt, 0u);
            __threadfence();
            atomicExch(&g_bar_gen, gen + 1u);
        } else {
            while (*(volatile unsigned*)&g_bar_gen == gen) { }
        }
        __threadfence();
    }
    __syncthreads();
}

// =====================================================================
// Phase 1: Gx[t][n][b] = (x@W[0:256,:])[r=t*32+b, n] + bias[n]
// M-tile 128 (rows r), N-tile 64, K-tile 16; thread tile 8m x 4n, f32x2 over m.
// =====================================================================
__global__ void __launch_bounds__(256) gemm_x(const float* __restrict__ x,
                                              const float* __restrict__ W,
                                              const float* __restrict__ bias) {
    __shared__ float As[16 * 128];   // [k][m]
    __shared__ float Bsd[16 * 128];  // [k][n duplicated x2]

    int tid = threadIdx.x;
    int mt = tid & 15, nt = tid >> 4;
    int rbase = blockIdx.y * 128;
    int nb = blockIdx.x * 64;

    ull acc[4][4];
#pragma unroll
    for (int i = 0; i < 4; ++i)
#pragma unroll
        for (int j = 0; j < 4; ++j) acc[i][j] = 0ull;

    for (int kt = 0; kt < 16; ++kt) {
        {   // stage X tile: 128 rows x 16 k
            int row = tid >> 1, half = tid & 1;
            int r = rbase + row;
            int b = r & 31, t = r >> 5;
            const float* xp = x + ((size_t)b * T_LEN + t) * DIN + kt * 16 + half * 8;
            float4 v0 = *(const float4*)xp;
            float4 v1 = *(const float4*)(xp + 4);
            int ko = half * 8;
            As[(ko + 0) * 128 + row] = v0.x;
            As[(ko + 1) * 128 + row] = v0.y;
            As[(ko + 2) * 128 + row] = v0.z;
            As[(ko + 3) * 128 + row] = v0.w;
            As[(ko + 4) * 128 + row] = v1.x;
            As[(ko + 5) * 128 + row] = v1.y;
            As[(ko + 6) * 128 + row] = v1.z;
            As[(ko + 7) * 128 + row] = v1.w;
        }
        {   // stage W tile duplicated: 16 k x 64 n
            int k = tid >> 4;
            int nn = (tid & 15) * 4;
            float4 wv = *(const float4*)(W + (size_t)(kt * 16 + k) * NG + nb + nn);
            float4 d0 = make_float4(wv.x, wv.x, wv.y, wv.y);
            float4 d1 = make_float4(wv.z, wv.z, wv.w, wv.w);
            *(float4*)&Bsd[k * 128 + nn * 2]     = d0;
            *(float4*)&Bsd[k * 128 + nn * 2 + 4] = d1;
        }
        __syncthreads();
#pragma unroll
        for (int k = 0; k < 16; ++k) {
            ulonglong2 a01 = *(const ulonglong2*)&As[k * 128 + mt * 8];
            ulonglong2 a23 = *(const ulonglong2*)&As[k * 128 + mt * 8 + 4];
            ulonglong2 b01 = *(const ulonglong2*)&Bsd[k * 128 + nt * 8];
            ulonglong2 b23 = *(const ulonglong2*)&Bsd[k * 128 + nt * 8 + 4];
            ull am[4] = {a01.x, a01.y, a23.x, a23.y};
            ull bd[4] = {b01.x, b01.y, b23.x, b23.y};
#pragma unroll
            for (int mp = 0; mp < 4; ++mp)
#pragma unroll
                for (int nn = 0; nn < 4; ++nn)
                    acc[mp][nn] = fma2(am[mp], bd[nn], acc[mp][nn]);
        }
        __syncthreads();
    }
#pragma unroll
    for (int mp = 0; mp < 4; ++mp) {
        int m = mt * 8 + mp * 2;          // even -> (b, b+1) share t
        int r = rbase + m;
        int b = r & 31, t = r >> 5;
#pragma unroll
        for (int nn = 0; nn < 4; ++nn) {
            int n = nb + nt * 4 + nn;
            float bv = __ldg(bias + n);
            float2 v = *(float2*)&acc[mp][nn];
            v.x += bv; v.y += bv;
            *(float2*)&g_Gx[((size_t)t * NG + n) * BATCH + b] = v;
        }
    }
}

// =====================================================================
// Phase 2: persistent recurrence. CTA g owns h-cols {2g,2g+1} -> 8 gate cols.
// Warp w handles k in [32w,32w+32); lane: p=lane&15 batch-pair, cg=lane>>4
// col-group (4 cols). Cross-warp k-reduction via smem partials.
// =====================================================================
__global__ void __launch_bounds__(256) lstm_rec(const float* __restrict__ W,
                                                const int* __restrict__ seq_lens,
                                                const float* __restrict__ c_in,
                                                const float* __restrict__ h_in,
                                                float* __restrict__ out) {
    extern __shared__ float sm[];
    float* ws   = sm;                   // 4096 f: dup weights [k][16]
    float* hs   = sm + 4096;            // 8192 f: h [k][b]
    ull*   ps2  = (ull*)(sm + 12288);   // 1152 ull: partials, pad 9
    float* gred = sm + 14592;           // 256 f: reduced gates [col][b]

    int tid = threadIdx.x;
    int g = blockIdx.x;
    int n0 = g * 2;

    {   // preload duplicated recurrent weights (constant across steps)
        int k = tid;
#pragma unroll
        for (int c8 = 0; c8 < 8; ++c8) {
            int gcol = (c8 >> 1) * HID + n0 + (c8 & 1);
            float wv = W[(size_t)(DIN + k) * NG + gcol];
            ws[k * 16 + c8 * 2]     = wv;
            ws[k * 16 + c8 * 2 + 1] = wv;
        }
    }

    int cc = tid >> 5;      // for tid<64: local h-col 0/1
    int bb = tid & 31;      // batch
    float creg = 0.f, hreg = 0.f;
    int slen = 0;
    if (tid < 64) {
        int n = n0 + cc;
        creg = c_in[bb * HID + n];
        hreg = h_in[bb * HID + n];
        slen = seq_lens[bb];
        g_hT[0][n * BATCH + bb] = hreg;
    }

    int lane = tid & 31, wrp = tid >> 5;
    int p = lane & 15, cg = lane >> 4;
    int kbase = wrp * 32;
    float* outLL = out + (size_t)BATCH * T_LEN * AOUT;

#pragma unroll 1
    for (int t = 0; t < T_LEN; ++t) {
        grid_barrier();
        int buf = t & 1;

        // prefetch precomputed input gates ([t][n][b] -> coalesced)
        float gx0 = 0.f, gx1 = 0.f, gx2 = 0.f, gx3 = 0.f;
        if (tid < 64) {
            const float* gp = g_Gx + ((size_t)t * NG + n0 + cc) * BATCH + bb;
            gx0 = gp[0];
            gx1 = gp[(size_t)256 * BATCH];
            gx2 = gp[(size_t)512 * BATCH];
            gx3 = gp[(size_t)768 * BATCH];
        }

        // stage full h [256x32] from L2 into smem
        const float* hg = g_hT[buf];
#pragma unroll
        for (int j2 = 0; j2 < 8; ++j2) {
            int idx = j2 * 1024 + tid * 4;
            *(float4*)&hs[idx] = *(const float4*)&hg[idx];
        }
        __syncthreads();

        // h @ Wh slice: 32 k's per warp, 4 cols x 2 batches per lane
        ull a0 = 0, a1 = 0, a2 = 0, a3 = 0;
#pragma unroll
        for (int kk = 0; kk < 32; ++kk) {
            int k = kbase + kk;
            ull h2 = *(const ull*)&hs[k * 32 + p * 2];
            ulonglong2 wa = *(const ulonglong2*)&ws[k * 16 + cg * 8];
            ulonglong2 wb = *(const ulonglong2*)&ws[k * 16 + cg * 8 + 4];
            a0 = fma2(h2, wa.x, a0);
            a1 = fma2(h2, wa.y, a1);
            a2 = fma2(h2, wb.x, a2);
            a3 = fma2(h2, wb.y, a3);
        }
        int cb = cg * 4;
        ps2[((cb + 0) * 16 + p) * 9 + wrp] = a0;
        ps2[((cb + 1) * 16 + p) * 9 + wrp] = a1;
        ps2[((cb + 2) * 16 + p) * 9 + wrp] = a2;
        ps2[((cb + 3) * 16 + p) * 9 + wrp] = a3;
        __syncthreads();

        if (tid < 128) {   // cross-warp k-reduction
            int col = tid >> 4, pp = tid & 15;
            const ull* base = ps2 + ((size_t)col * 16 + pp) * 9;
            float sx = 0.f, sy = 0.f;
#pragma unroll
            for (int w2 = 0; w2 < 8; ++w2) {
                float2 f = *(const float2*)&base[w2];
                sx += f.x; sy += f.y;
            }
            gred[col * 32 + pp * 2]     = sx;
            gred[col * 32 + pp * 2 + 1] = sy;
        }
        __syncthreads();

        if (tid < 64) {    // activations + state update + outputs
            int n = n0 + cc;
            float gi = gred[(0 * 2 + cc) * 32 + bb] + gx0;
            float gj = gred[(1 * 2 + cc) * 32 + bb] + gx1;
            float gf = gred[(2 * 2 + cc) * 32 + bb] + gx2;
            float go = gred[(3 * 2 + cc) * 32 + bb] + gx3;
            float sf = 1.f / (1.f + __expf(-(gf + 1.f)));   // FORGET_BIAS = 1
            float si = 1.f / (1.f + __expf(-gi));
            float so = 1.f / (1.f + __expf(-go));
            float nc = creg * sf + si * tanhf(gj);
            float nh = tanhf(nc) * so;
            bool mvalid = (t < slen);
            if (mvalid) { creg = nc; hreg = nh; }
            outLL[((size_t)bb * T_LEN + t) * HID + n] = mvalid ? nh : 0.f;
            g_hT[buf ^ 1][n * BATCH + bb] = hreg;
        }
    }

    if (tid < 64) {   // finals
        int n = n0 + cc;
        float* cf = out + (size_t)BATCH * T_LEN * AOUT + (size_t)BATCH * T_LEN * HID;
        float* hf = cf + BATCH * HID;
        cf[bb * HID + n] = creg;
        hf[bb * HID + n] = hreg;
    }
}

// =====================================================================
// Phase 3: logits = last_layer @ W_out + b_out.  288 = 16 rows x 18 cols.
// =====================================================================
#define PROJ_TPB 288
__global__ void __launch_bounds__(PROJ_TPB) proj_kernel(const float* __restrict__ LL,
                                                        const float* __restrict__ Wo,
                                                        const float* __restrict__ bo,
                                                        float* __restrict__ logits,
                                                        int tiles_per_block) {
    __shared__ float Wsm[256 * 18];
    __shared__ float Lsm[16 * 257];   // pad 257 -> conflict-free column reads

    int tid = threadIdx.x;
    for (int i = tid; i < 256 * 18; i += PROJ_TPB) Wsm[i] = Wo[i];
    int r = tid / 18;
    int a = tid - r * 18;
    float bv = bo[a];

    for (int tile = 0; tile < tiles_per_block; ++tile) {
        int rbase = (blockIdx.x * tiles_per_block + tile) * 16;
        __syncthreads();
        for (int i = tid; i < 16 * 256; i += PROJ_TPB) {
            int rr = i >> 8, c = i & 255;
            Lsm[rr * 257 + c] = LL[(size_t)rbase * 256 + i];
        }
        __syncthreads();
        float acc = 0.f;
        const float* lr = &Lsm[r * 257];
#pragma unroll 8
        for (int h = 0; h < 256; ++h)
            acc = fmaf(lr[h], Wsm[h * 18 + a], acc);
        logits[(size_t)(rbase + r) * AOUT + a] = acc + bv;
    }
}

// =====================================================================
extern "C" void kernel_launch(void* const* d_in, const int* in_sizes, int n_in,
                              void* d_out, int out_size) {
    const float* x        = (const float*)d_in[0];
    const int*   seq_lens = (const int*)  d_in[1];
    const float* c_in     = (const float*)d_in[2];
    const float* h_in     = (const float*)d_in[3];
    const float* W        = (const float*)d_in[4];
    const float* b        = (const float*)d_in[5];
    const float* W_out    = (const float*)d_in[6];
    const float* b_out    = (const float*)d_in[7];
    float* out = (float*)d_out;

    static bool attr_done = false;
    if (!attr_done) {
        cudaFuncSetAttribute(lstm_rec, cudaFuncAttributeMaxDynamicSharedMemorySize, 59392);
        attr_done = true;
    }

    // Phase 1: input GEMM for all timesteps
    gemm_x<<<dim3(16, 512), 256>>>(x, W, b);

    // Phase 2: persistent recurrence (writes last_layer, c_fin, h_fin)
    lstm_rec<<<GBLK, 256, 59392>>>(W, seq_lens, c_in, h_in, out);

    // Phase 3: output projection (reads last_layer from out)
    const float* LL = out + (size_t)BATCH * T_LEN * AOUT;
    proj_kernel<<<512, PROJ_TPB>>>(LL, W_out, b_out, out, 8);
}